// round 7
// baseline (speedup 1.0000x reference)
#include <cuda_runtime.h>
#include <cuda_bf16.h>
#include <cstdint>
#include <math.h>

#define BB      4
#define LL      1024
#define DIMV    512
#define VOCABN  10000
#define DEPTHN  3
#define DSTATE  16
#define DCONVN  4
#define DINNER  1024
#define DTRANK  32
#define HEADSN  8
#define DH      64
#define CTXN    98
#define NROWS   (BB*LL)          /* 4096 */

typedef unsigned int u32;

// ---------------- fp32 scratch ----------------
__device__ float g_h[NROWS*DIMV];
__device__ float g_xz[NROWS*2*DINNER];
__device__ float g_u[NROWS*DINNER];
__device__ float g_xdbl[NROWS*(DTRANK+2*DSTATE)];
__device__ float g_delta[NROWS*DINNER];
__device__ float g_q[NROWS*DIMV];
__device__ float g_kv[BB*CTXN*2*DIMV];
__device__ float g_probs[BB*HEADSN*LL*CTXN];

// ---------------- bf16 hi/lo plane scratch (activations) ----------------
__device__ __nv_bfloat16 g_nrm_h[NROWS*DIMV],  g_nrm_l[NROWS*DIMV];
__device__ __nv_bfloat16 g_u_h[NROWS*DINNER],  g_u_l[NROWS*DINNER];
__device__ __nv_bfloat16 g_xd_h[NROWS*64],     g_xd_l[NROWS*64];
__device__ __nv_bfloat16 g_y_h[NROWS*DINNER],  g_y_l[NROWS*DINNER];
__device__ __nv_bfloat16 g_ao_h[NROWS*DIMV],   g_ao_l[NROWS*DIMV];
__device__ __nv_bfloat16 g_ctx_h[BB*CTXN*DIMV],g_ctx_l[BB*CTXN*DIMV];

// ---------------- bf16 hi/lo plane scratch (weights) ----------------
__device__ __nv_bfloat16 g_wi_h[DEPTHN*2*DINNER*DIMV], g_wi_l[DEPTHN*2*DINNER*DIMV];
__device__ __nv_bfloat16 g_wxp_h[DEPTHN*64*DINNER],    g_wxp_l[DEPTHN*64*DINNER];
__device__ __nv_bfloat16 g_wdt_h[DEPTHN*DINNER*DTRANK],g_wdt_l[DEPTHN*DINNER*DTRANK];
__device__ __nv_bfloat16 g_wmo_h[DEPTHN*DIMV*DINNER],  g_wmo_l[DEPTHN*DIMV*DINNER];
__device__ __nv_bfloat16 g_wai_h[DEPTHN*3*DIMV*DIMV],  g_wai_l[DEPTHN*3*DIMV*DIMV];
__device__ __nv_bfloat16 g_wao_h[DEPTHN*DIMV*DIMV],    g_wao_l[DEPTHN*DIMV*DIMV];
__device__ __nv_bfloat16 g_wlg_h[VOCABN*DIMV],         g_wlg_l[VOCABN*DIMV];

__device__ __forceinline__ float siluf(float x) {
    return x / (1.0f + __expf(-x));
}

__device__ __forceinline__ void stage_split(float v, __nv_bfloat16* hp, __nv_bfloat16* lp) {
    __nv_bfloat16 h = __float2bfloat16(v);
    *hp = h;
    *lp = __float2bfloat16(v - __bfloat162float(h));
}

__device__ __forceinline__ u32 ld32bf(const __nv_bfloat16* p) {
    return *reinterpret_cast<const u32*>(p);
}

__device__ __forceinline__ void mma16816(float* c, const u32* a, const u32* b) {
    asm volatile(
        "mma.sync.aligned.m16n8k16.row.col.f32.bf16.bf16.f32 "
        "{%0,%1,%2,%3}, {%4,%5,%6,%7}, {%8,%9}, {%0,%1,%2,%3};\n"
        : "+f"(c[0]), "+f"(c[1]), "+f"(c[2]), "+f"(c[3])
        : "r"(a[0]), "r"(a[1]), "r"(a[2]), "r"(a[3]), "r"(b[0]), "r"(b[1]));
}

__device__ __forceinline__ void cp16(u32 dst, const void* src, int pbytes) {
    asm volatile("cp.async.cg.shared.global [%0], [%1], 16, %2;\n"
                 :: "r"(dst), "l"(src), "r"(pbytes));
}

// ---------------- fp32 -> (hi,lo) bf16 plane split ----------------
__global__ void split_k(const float* __restrict__ src,
                        __nv_bfloat16* __restrict__ hi,
                        __nv_bfloat16* __restrict__ lo, int n4)
{
    int i = blockIdx.x*blockDim.x + threadIdx.x;
    if (i >= n4) return;
    float4 v = ((const float4*)src)[i];
    __nv_bfloat16 h4[4], l4[4];
    stage_split(v.x, &h4[0], &l4[0]);
    stage_split(v.y, &h4[1], &l4[1]);
    stage_split(v.z, &h4[2], &l4[2]);
    stage_split(v.w, &h4[3], &l4[3]);
    ((uint2*)hi)[i] = *(uint2*)h4;
    ((uint2*)lo)[i] = *(uint2*)l4;
}

// =========================================================================
// Tensor-core GEMM on pre-split planes:
//   C[M,N] = (Ah+Al)[M,K] @ (Wh+Wl)[N,K]^T  (3-term, fp32 acc)
// flags: 1=beta (C += result), 2=softplus epilogue, 4=also write C planes
// Double-buffered cp.async staging. K % 32 == 0 required.
// =========================================================================
#define BKT 32
#define PROW 40   /* padded bf16 elems per smem row (80B, 16B-aligned) */

template<int BM_, int BN_, int WGM, int WGN>
__global__ void __launch_bounds__(256)
hgemm_k(const __nv_bfloat16* __restrict__ Ah_g, const __nv_bfloat16* __restrict__ Al_g, int lda,
        const __nv_bfloat16* __restrict__ Wh_g, const __nv_bfloat16* __restrict__ Wl_g, int ldw,
        const float* __restrict__ bias,
        float* __restrict__ C, __nv_bfloat16* __restrict__ Ch, __nv_bfloat16* __restrict__ Cl,
        int ldc, int M, int N, int K, int flags)
{
    constexpr int MT  = BM_/(WGM*16);
    constexpr int NT  = BN_/(WGN*8);
    constexpr int WMR = BM_/WGM;
    constexpr int WNC = BN_/WGN;

    extern __shared__ __nv_bfloat16 smem[];
    __nv_bfloat16* sA = smem;                   // [stage][plane][BM_*PROW]
    __nv_bfloat16* sW = smem + 2*2*BM_*PROW;    // [stage][plane][BN_*PROW]
    u32 sAu = (u32)__cvta_generic_to_shared(sA);
    u32 sWu = (u32)__cvta_generic_to_shared(sW);

    int bm = blockIdx.y*BM_, bn = blockIdx.x*BN_;
    int tid = threadIdx.x, warp = tid >> 5, lane = tid & 31;
    int wm = warp / WGN, wn = warp % WGN;
    int g = lane >> 2, cq = lane & 3;

    float acc[MT][NT][4];
#pragma unroll
    for (int mt = 0; mt < MT; mt++)
#pragma unroll
        for (int nt = 0; nt < NT; nt++)
#pragma unroll
            for (int j = 0; j < 4; j++) acc[mt][nt][j] = 0.f;

    auto load_stage = [&](int st, int k0) {
#pragma unroll
        for (int p = 0; p < 2; p++) {
            const __nv_bfloat16* s = p ? Al_g : Ah_g;
#pragma unroll
            for (int it = 0; it < (BM_*4)/256; it++) {
                int ci = tid + it*256;
                int r = ci >> 2, cc = (ci & 3) << 3;
                int gr = bm + r;
                u32 dst = sAu + (u32)((st*2+p)*BM_*PROW + r*PROW + cc)*2;
                cp16(dst, s + (long)(gr < M ? gr : 0)*lda + k0 + cc, gr < M ? 16 : 0);
            }
        }
#pragma unroll
        for (int p = 0; p < 2; p++) {
            const __nv_bfloat16* s = p ? Wl_g : Wh_g;
#pragma unroll
            for (int it = 0; it < (BN_*4)/256; it++) {
                int ci = tid + it*256;
                int r = ci >> 2, cc = (ci & 3) << 3;
                int gn = bn + r;
                u32 dst = sWu + (u32)((st*2+p)*BN_*PROW + r*PROW + cc)*2;
                cp16(dst, s + (long)(gn < N ? gn : 0)*ldw + k0 + cc, gn < N ? 16 : 0);
            }
        }
    };

    const int KT = K / BKT;
    load_stage(0, 0);
    asm volatile("cp.async.commit_group;\n");

    for (int kt = 0; kt < KT; kt++) {
        int cur = kt & 1;
        if (kt + 1 < KT) {
            load_stage((kt+1) & 1, (kt+1)*BKT);
            asm volatile("cp.async.commit_group;\n");
            asm volatile("cp.async.wait_group 1;\n");
        } else {
            asm volatile("cp.async.wait_group 0;\n");
        }
        __syncthreads();

        const __nv_bfloat16* Ahs = sA + (cur*2+0)*BM_*PROW;
        const __nv_bfloat16* Als = sA + (cur*2+1)*BM_*PROW;
        const __nv_bfloat16* Whs = sW + (cur*2+0)*BN_*PROW;
        const __nv_bfloat16* Wls = sW + (cur*2+1)*BN_*PROW;

#pragma unroll
        for (int ks = 0; ks < 2; ks++) {
            u32 ah[MT][4], al[MT][4], bh[NT][2], bl[NT][2];
#pragma unroll
            for (int mt = 0; mt < MT; mt++) {
                int base = (wm*WMR + mt*16 + g)*PROW + ks*16 + 2*cq;
                ah[mt][0] = ld32bf(&Ahs[base]);
                ah[mt][1] = ld32bf(&Ahs[base + 8*PROW]);
                ah[mt][2] = ld32bf(&Ahs[base + 8]);
                ah[mt][3] = ld32bf(&Ahs[base + 8*PROW + 8]);
                al[mt][0] = ld32bf(&Als[base]);
                al[mt][1] = ld32bf(&Als[base + 8*PROW]);
                al[mt][2] = ld32bf(&Als[base + 8]);
                al[mt][3] = ld32bf(&Als[base + 8*PROW + 8]);
            }
#pragma unroll
            for (int nt = 0; nt < NT; nt++) {
                int base = (wn*WNC + nt*8 + g)*PROW + ks*16 + 2*cq;
                bh[nt][0] = ld32bf(&Whs[base]);
                bh[nt][1] = ld32bf(&Whs[base + 8]);
                bl[nt][0] = ld32bf(&Wls[base]);
                bl[nt][1] = ld32bf(&Wls[base + 8]);
            }
#pragma unroll
            for (int mt = 0; mt < MT; mt++)
#pragma unroll
                for (int nt = 0; nt < NT; nt++) {
                    mma16816(acc[mt][nt], ah[mt], bh[nt]);
                    mma16816(acc[mt][nt], al[mt], bh[nt]);
                    mma16816(acc[mt][nt], ah[mt], bl[nt]);
                }
        }
        __syncthreads();
    }

    // ---- epilogue ----
#pragma unroll
    for (int mt = 0; mt < MT; mt++) {
        int r0 = bm + wm*WMR + mt*16 + g;
#pragma unroll
        for (int nt = 0; nt < NT; nt++) {
            int n0 = bn + wn*WNC + nt*8 + 2*cq;
            float bv0 = 0.f, bv1 = 0.f;
            if (bias) {
                if (n0   < N) bv0 = bias[n0];
                if (n0+1 < N) bv1 = bias[n0+1];
            }
#pragma unroll
            for (int half = 0; half < 2; half++) {
                int r = r0 + half*8;
                if (r >= M) continue;
                float v0 = acc[mt][nt][half*2+0] + bv0;
                float v1 = acc[mt][nt][half*2+1] + bv1;
                float* p = &C[(long)r*ldc + n0];
                if (flags & 1) {
                    if (n0   < N) v0 += p[0];
                    if (n0+1 < N) v1 += p[1];
                }
                if (flags & 2) {
                    v0 = (v0 > 20.f) ? v0 : log1pf(expf(v0));
                    v1 = (v1 > 20.f) ? v1 : log1pf(expf(v1));
                }
                if (n0+1 < N) {
                    *(float2*)p = make_float2(v0, v1);
                } else if (n0 < N) {
                    p[0] = v0;
                }
                if (flags & 4) {
                    long o = (long)r*ldc + n0;
                    if (n0   < N) stage_split(v0, &Ch[o],   &Cl[o]);
                    if (n0+1 < N) stage_split(v1, &Ch[o+1], &Cl[o+1]);
                }
            }
        }
    }
}

// ---------------- layernorm -> bf16 planes ----------------
__global__ void __launch_bounds__(256)
layernorm_k(const float* __restrict__ x, const float* __restrict__ g,
            const float* __restrict__ bta,
            __nv_bfloat16* __restrict__ nh, __nv_bfloat16* __restrict__ nl)
{
    int row = blockIdx.x;
    const float* xr = x + (long)row*DIMV;
    int tid = threadIdx.x;
    float v0 = xr[tid], v1 = xr[tid+256];

    __shared__ float red[8];
    float s = v0 + v1;
#pragma unroll
    for (int o = 16; o; o >>= 1) s += __shfl_xor_sync(0xffffffffu, s, o);
    if ((tid & 31) == 0) red[tid >> 5] = s;
    __syncthreads();
    if (tid < 8) {
        s = red[tid];
#pragma unroll
        for (int o = 4; o; o >>= 1) s += __shfl_xor_sync(0xffu, s, o);
        if (tid == 0) red[0] = s;
    }
    __syncthreads();
    float mu = red[0] * (1.0f/DIMV);
    float d0 = v0 - mu, d1 = v1 - mu;

    __shared__ float red2[8];
    float qv = d0*d0 + d1*d1;
#pragma unroll
    for (int o = 16; o; o >>= 1) qv += __shfl_xor_sync(0xffffffffu, qv, o);
    if ((tid & 31) == 0) red2[tid >> 5] = qv;
    __syncthreads();
    if (tid < 8) {
        qv = red2[tid];
#pragma unroll
        for (int o = 4; o; o >>= 1) qv += __shfl_xor_sync(0xffu, qv, o);
        if (tid == 0) red2[0] = qv;
    }
    __syncthreads();
    float rstd = rsqrtf(red2[0] * (1.0f/DIMV) + 1e-5f);
    float o0 = d0*rstd*g[tid]     + bta[tid];
    float o1 = d1*rstd*g[tid+256] + bta[tid+256];
    long base = (long)row*DIMV;
    stage_split(o0, &nh[base + tid],       &nl[base + tid]);
    stage_split(o1, &nh[base + tid + 256], &nl[base + tid + 256]);
}

// ---------------- embedding ----------------
__global__ void embed_k(const int* __restrict__ x, const float* __restrict__ tok,
                        const float* __restrict__ pos)
{
    int idx = blockIdx.x*blockDim.x + threadIdx.x;
    if (idx >= NROWS*DIMV) return;
    int d = idx & (DIMV-1);
    int row = idx >> 9;
    int l = row & (LL-1);
    int t = x[row];
    g_h[idx] = tok[(long)t*DIMV + d] + pos[(long)l*DIMV + d];
}

// ---------------- causal depthwise conv + silu -> u fp32 + planes ----------
__global__ void conv_silu_k(const float* __restrict__ w, const float* __restrict__ cb)
{
    int idx = blockIdx.x*blockDim.x + threadIdx.x;
    if (idx >= NROWS*DINNER) return;
    int d = idx & (DINNER-1);
    int row = idx >> 10;
    int l = row & (LL-1);
    int b = row >> 10;
    float acc = cb[d];
#pragma unroll
    for (int j = 0; j < DCONVN; j++) {
        int ll = l - (DCONVN-1) + j;
        if (ll >= 0)
            acc += w[d*DCONVN + j] * g_xz[((long)(b*LL + ll))*(2*DINNER) + d];
    }
    float r = siluf(acc);
    g_u[idx] = r;
    stage_split(r, &g_u_h[idx], &g_u_l[idx]);
}

// ---------------- selective scan, fused gate + plane output ----------------
__global__ void __launch_bounds__(256)
scan_k(const float* __restrict__ A_log, const float* __restrict__ D_skip)
{
    int b = blockIdx.y;
    int dbase = blockIdx.x * 16;
    int tid = threadIdx.x;
    int w = tid >> 5, lane = tid & 31;
    int d = dbase + (w << 1) + (lane >> 4);
    int s = lane & 15;

    float a  = -__expf(A_log[d*DSTATE + s]);
    float Dv = D_skip[d];
    float h  = 0.f;

    const float* dl = g_delta + (long)b*LL*DINNER + d;
    const float* uu = g_u     + (long)b*LL*DINNER + d;
    const float* bc = g_xdbl  + (long)b*LL*(DTRANK+2*DSTATE);
    const float* zz = g_xz    + ((long)b*LL)*(2*DINNER) + DINNER + d;
    __nv_bfloat16* yh = g_y_h + (long)b*LL*DINNER + d;
    __nv_bfloat16* yl = g_y_l + (long)b*LL*DINNER + d;

#pragma unroll 4
    for (int t = 0; t < LL; t++) {
        float dt = dl[(long)t*DINNER];
        float ut = uu[(long)t*DINNER];
        float Bt = bc[t*64 + DTRANK + s];
        float Ct = bc[t*64 + DTRANK + DSTATE + s];
        h = __expf(dt*a)*h + (dt*ut)*Bt;
        float p = h*Ct;
        p += __shfl_xor_sync(0xffffffffu, p, 8);
        p += __shfl_xor_sync(0xffffffffu, p, 4);
        p += __shfl_xor_sync(0xffffffffu, p, 2);
        p += __shfl_xor_sync(0xffffffffu, p, 1);
        if (s == 0) {
            float z = zz[(long)t*(2*DINNER)];
            float yv = (p + ut*Dv) * siluf(z);
            stage_split(yv, &yh[(long)t*DINNER], &yl[(long)t*DINNER]);
        }
    }
}

// ---------------- attention scores: grid (B*H, L/128), 128 thr ----------
__global__ void __launch_bounds__(128)
attn_scores_k()
{
    __shared__ float ks[CTXN*DH];
    int bh = blockIdx.x;
    int b = bh >> 3, hh = bh & 7;
    for (int i = threadIdx.x; i < CTXN*DH; i += 128)
        ks[i] = g_kv[((long)(b*CTXN + (i >> 6)))*(2*DIMV) + hh*DH + (i & 63)];
    __syncthreads();

    int l = blockIdx.y*128 + threadIdx.x;
    float qr[DH];
    const float* qp = g_q + ((long)(b*LL + l))*DIMV + hh*DH;
#pragma unroll
    for (int j = 0; j < DH; j++) qr[j] = qp[j];

    float* sp = g_probs + ((long)(bh*LL + l))*CTXN;
    for (int ss = 0; ss < CTXN; ss++) {
        float acc = 0.f;
#pragma unroll
        for (int j = 0; j < DH; j++) acc += qr[j]*ks[ss*DH + j];
        sp[ss] = acc * 0.125f;
    }
}

// ---------------- softmax over S=98: one warp per row ----------------
__global__ void __launch_bounds__(256)
softmax_k()
{
    int row = blockIdx.x*8 + (threadIdx.x >> 5);
    int lane = threadIdx.x & 31;
    float* p = g_probs + (long)row*CTXN;
    float v0 = p[lane];
    float v1 = p[lane+32];
    float v2 = p[lane+64];
    float v3 = (lane+96 < CTXN) ? p[lane+96] : -1e30f;
    float m = fmaxf(fmaxf(v0,v1), fmaxf(v2,v3));
#pragma unroll
    for (int o = 16; o; o >>= 1) m = fmaxf(m, __shfl_xor_sync(0xffffffffu, m, o));
    v0 = __expf(v0 - m); v1 = __expf(v1 - m); v2 = __expf(v2 - m);
    v3 = (lane+96 < CTXN) ? __expf(v3 - m) : 0.f;
    float s = v0+v1+v2+v3;
#pragma unroll
    for (int o = 16; o; o >>= 1) s += __shfl_xor_sync(0xffffffffu, s, o);
    float inv = 1.f/s;
    p[lane] = v0*inv; p[lane+32] = v1*inv; p[lane+64] = v2*inv;
    if (lane+96 < CTXN) p[lane+96] = v3*inv;
}

// ---------------- attn head-mean -> d_out region ----------------
__global__ void attn_mean_k(float* __restrict__ outp)
{
    int idx = blockIdx.x*blockDim.x + threadIdx.x;
    if (idx >= BB*LL*CTXN) return;
    int s = idx % CTXN;
    int bl = idx / CTXN;
    int l = bl & (LL-1);
    int b = bl >> 10;
    float acc = 0.f;
#pragma unroll
    for (int hh = 0; hh < HEADSN; hh++)
        acc += g_probs[((long)((b*HEADSN + hh)*LL + l))*CTXN + s];
    outp[idx] = acc * (1.0f/HEADSN);
}

// ---------------- attn @ V -> ao planes ----------------
__global__ void __launch_bounds__(128)
attn_av_k()
{
    __shared__ float vs[CTXN*DH];
    int bh = blockIdx.x;
    int b = bh >> 3, hh = bh & 7;
    for (int i = threadIdx.x; i < CTXN*DH; i += 128)
        vs[i] = g_kv[((long)(b*CTXN + (i >> 6)))*(2*DIMV) + DIMV + hh*DH + (i & 63)];
    __syncthreads();

    int l = blockIdx.y*128 + threadIdx.x;
    const float* pp = g_probs + ((long)(bh*LL + l))*CTXN;
    float acc[DH];
#pragma unroll
    for (int j = 0; j < DH; j++) acc[j] = 0.f;
    for (int ss = 0; ss < CTXN; ss++) {
        float pv = pp[ss];
#pragma unroll
        for (int j = 0; j < DH; j++) acc[j] += pv*vs[ss*DH + j];
    }
    long off = ((long)(b*LL + l))*DIMV + hh*DH;
#pragma unroll
    for (int j = 0; j < DH; j++)
        stage_split(acc[j], &g_ao_h[off + j], &g_ao_l[off + j]);
}

// =======================================================================
typedef __nv_bfloat16 bf;

extern "C" void kernel_launch(void* const* d_in, const int* in_sizes, int n_in,
                              void* d_out, int out_size)
{
    (void)in_sizes; (void)n_in; (void)out_size;
    const int*   x          = (const int*)  d_in[0];
    const float* context    = (const float*)d_in[1];
    const float* tok_emb    = (const float*)d_in[2];
    const float* pos_emb    = (const float*)d_in[3];
    const float* ln1_g      = (const float*)d_in[4];
    const float* ln1_b      = (const float*)d_in[5];
    const float* in_w       = (const float*)d_in[6];
    const float* conv_w     = (const float*)d_in[7];
    const float* conv_b     = (const float*)d_in[8];
    const float* xproj_w    = (const float*)d_in[9];
    const float* dt_w       = (const float*)d_in[10];
    const float* dt_b       = (const float*)d_in[11];
    const float* A_log      = (const float*)d_in[12];
    const float* D_skip     = (const float*)d_in[13];
    const float* mamba_out_w= (const float*)d_in[14];
    const float* ln2_g      = (const float*)d_in[15];
    const float* ln2_b      = (const float*)d_in[16];
    const float* attn_in_w  = (const float*)d_in[17];
    const float* attn_in_b  = (const float*)d_in[18];
    const float* attn_out_w = (const float*)d_in[19];
    const float* attn_out_b = (const float*)d_in[20];
    const float* lnf_g      = (const float*)d_in[21];
    const float* lnf_b      = (const float*)d_in[22];
    const float* logit_w    = (const float*)d_in[23];
    const float* logit_b    = (const float*)d_in[24];
    float* outp = (float*)d_out;

    // symbol addresses
    float *h, *xz, *u, *xdbl, *delta, *q, *kv;
    cudaGetSymbolAddress((void**)&h,    g_h);
    cudaGetSymbolAddress((void**)&xz,   g_xz);
    cudaGetSymbolAddress((void**)&u,    g_u);
    cudaGetSymbolAddress((void**)&xdbl, g_xdbl);
    cudaGetSymbolAddress((void**)&delta,g_delta);
    cudaGetSymbolAddress((void**)&q,    g_q);
    cudaGetSymbolAddress((void**)&kv,   g_kv);
    bf *nrmh,*nrml,*uh,*ul,*xdh,*xdl,*yh,*yl,*aoh,*aol,*ctxh,*ctxl;
    cudaGetSymbolAddress((void**)&nrmh, g_nrm_h); cudaGetSymbolAddress((void**)&nrml, g_nrm_l);
    cudaGetSymbolAddress((void**)&uh,   g_u_h);   cudaGetSymbolAddress((void**)&ul,   g_u_l);
    cudaGetSymbolAddress((void**)&xdh,  g_xd_h);  cudaGetSymbolAddress((void**)&xdl,  g_xd_l);
    cudaGetSymbolAddress((void**)&yh,   g_y_h);   cudaGetSymbolAddress((void**)&yl,   g_y_l);
    cudaGetSymbolAddress((void**)&aoh,  g_ao_h);  cudaGetSymbolAddress((void**)&aol,  g_ao_l);
    cudaGetSymbolAddress((void**)&ctxh, g_ctx_h); cudaGetSymbolAddress((void**)&ctxl, g_ctx_l);
    bf *wih,*wil,*wxph,*wxpl,*wdth,*wdtl,*wmoh,*wmol,*waih,*wail,*waoh,*waol,*wlgh,*wlgl;
    cudaGetSymbolAddress((void**)&wih,  g_wi_h);  cudaGetSymbolAddress((void**)&wil,  g_wi_l);
    cudaGetSymbolAddress((void**)&wxph, g_wxp_h); cudaGetSymbolAddress((void**)&wxpl, g_wxp_l);
    cudaGetSymbolAddress((void**)&wdth, g_wdt_h); cudaGetSymbolAddress((void**)&wdtl, g_wdt_l);
    cudaGetSymbolAddress((void**)&wmoh, g_wmo_h); cudaGetSymbolAddress((void**)&wmol, g_wmo_l);
    cudaGetSymbolAddress((void**)&waih, g_wai_h); cudaGetSymbolAddress((void**)&wail, g_wai_l);
    cudaGetSymbolAddress((void**)&waoh, g_wao_h); cudaGetSymbolAddress((void**)&waol, g_wao_l);
    cudaGetSymbolAddress((void**)&wlgh, g_wlg_h); cudaGetSymbolAddress((void**)&wlgl, g_wlg_l);

    // dynamic smem opt-in (once per call; cheap, capture-safe)
    constexpr int SM128 = (128+128)*2*2*PROW*2;
    constexpr int SM64  = (64+64)  *2*2*PROW*2;
    constexpr int SM64128 = (64+128)*2*2*PROW*2;
    cudaFuncSetAttribute((const void*)hgemm_k<128,128,2,4>,
                         cudaFuncAttributeMaxDynamicSharedMemorySize, SM128);
    cudaFuncSetAttribute((const void*)hgemm_k<64,64,4,2>,
                         cudaFuncAttributeMaxDynamicSharedMemorySize, SM64);
    cudaFuncSetAttribute((const void*)hgemm_k<64,128,2,4>,
                         cudaFuncAttributeMaxDynamicSharedMemorySize, SM64128);

    const int NTH = 256;
    auto split = [&](const float* src, bf* hi, bf* lo, long n) {
        int n4 = (int)(n/4);
        split_k<<<(n4 + NTH-1)/NTH, NTH>>>(src, hi, lo, n4);
    };

    // ---- one-time weight/context splits ----
    split(in_w,       wih,  wil,  (long)DEPTHN*2*DINNER*DIMV);
    split(xproj_w,    wxph, wxpl, (long)DEPTHN*64*DINNER);
    split(dt_w,       wdth, wdtl, (long)DEPTHN*DINNER*DTRANK);
    split(mamba_out_w,wmoh, wmol, (long)DEPTHN*DIMV*DINNER);
    split(attn_in_w,  waih, wail, (long)DEPTHN*3*DIMV*DIMV);
    split(attn_out_w, waoh, waol, (long)DEPTHN*DIMV*DIMV);
    split(logit_w,    wlgh, wlgl, (long)VOCABN*DIMV);
    split(context,    ctxh, ctxl, (long)BB*CTXN*DIMV);

    auto gemm128 = [&](const bf* Ahp, const bf* Alp, int lda,
                       const bf* Whp, const bf* Wlp, int ldw,
                       const float* bias, float* C, bf* Chp, bf* Clp, int ldc,
                       int M, int N, int K, int flags) {
        dim3 grid((N + 127)/128, (M + 127)/128);
        hgemm_k<128,128,2,4><<<grid, 256, SM128>>>(Ahp,Alp,lda, Whp,Wlp,ldw,
                                                   bias, C,Chp,Clp, ldc, M,N,K, flags);
    };

    embed_k<<<(NROWS*DIMV + NTH-1)/NTH, NTH>>>(x, tok_emb, pos_emb);

    for (int i = 0; i < DEPTHN; i++) {
        // ---- mamba block ----
        layernorm_k<<<NROWS, 256>>>(h, ln1_g + i*DIMV, ln1_b + i*DIMV, nrmh, nrml);
        gemm128(nrmh, nrml, DIMV, wih + (long)i*2*DINNER*DIMV, wil + (long)i*2*DINNER*DIMV,
                DIMV, nullptr, xz, nullptr, nullptr, 2*DINNER, NROWS, 2*DINNER, DIMV, 0);
        conv_silu_k<<<(NROWS*DINNER + NTH-1)/NTH, NTH>>>(
            conv_w + (long)i*DINNER*DCONVN, conv_b + (long)i*DINNER);
        {   // xproj: N=64 -> 64x64 tiles
            dim3 grid(1, NROWS/64);
            hgemm_k<64,64,4,2><<<grid, 256, SM64>>>(
                uh, ul, DINNER, wxph + (long)i*64*DINNER, wxpl + (long)i*64*DINNER,
                DINNER, nullptr, xdbl, xdh, xdl, 64, NROWS, 64, DINNER, 4 /*planes*/);
        }
        gemm128(xdh, xdl, 64, wdth + (long)i*DINNER*DTRANK, wdtl + (long)i*DINNER*DTRANK,
                DTRANK, dt_b + (long)i*DINNER, delta, nullptr, nullptr, DINNER,
                NROWS, DINNER, DTRANK, 2 /*softplus*/);
        scan_k<<<dim3(DINNER/16, BB), 256>>>(
            A_log + (long)i*DINNER*DSTATE, D_skip + (long)i*DINNER);
        gemm128(yh, yl, DINNER, wmoh + (long)i*DIMV*DINNER, wmol + (long)i*DIMV*DINNER,
                DINNER, nullptr, h, nullptr, nullptr, DIMV, NROWS, DIMV, DINNER, 1 /*beta*/);

        // ---- cross attention ----
        layernorm_k<<<NROWS, 256>>>(h, ln2_g + i*DIMV, ln2_b + i*DIMV, nrmh, nrml);
        long aiw_off = (long)i*3*DIMV*DIMV;
        const float* ab = attn_in_b + (long)i*3*DIMV;
        gemm128(nrmh, nrml, DIMV, waih + aiw_off, wail + aiw_off, DIMV,
                ab, q, nullptr, nullptr, DIMV, NROWS, DIMV, DIMV, 0);
        {   // fused K+V projection: M=392, N=1024 -> 64x128 tiles
            dim3 grid((2*DIMV)/128, (BB*CTXN + 63)/64);
            hgemm_k<64,128,2,4><<<grid, 256, SM64128>>>(
                ctxh, ctxl, DIMV, waih + aiw_off + (long)DIMV*DIMV,
                wail + aiw_off + (long)DIMV*DIMV, DIMV,
                ab + DIMV, kv, nullptr, nullptr, 2*DIMV, BB*CTXN, 2*DIMV, DIMV, 0);
        }
        attn_scores_k<<<dim3(BB*HEADSN, LL/128), 128>>>();
        softmax_k<<<(BB*HEADSN*LL)/8, 256>>>();
        attn_mean_k<<<(BB*LL*CTXN + NTH-1)/NTH, NTH>>>(
            outp + (long)BB*LL*VOCABN + (long)i*BB*LL*CTXN);
        attn_av_k<<<dim3(BB*HEADSN, LL/128), 128>>>();
        gemm128(aoh, aol, DIMV, waoh + (long)i*DIMV*DIMV, waol + (long)i*DIMV*DIMV,
                DIMV, attn_out_b + (long)i*DIMV, h, nullptr, nullptr, DIMV,
                NROWS, DIMV, DIMV, 1 /*beta*/);
    }

    // ---- final LN + logits ----
    layernorm_k<<<NROWS, 256>>>(h, lnf_g, lnf_b, nrmh, nrml);
    gemm128(nrmh, nrml, DIMV, wlgh, wlgl, DIMV, logit_b, outp,
            nullptr, nullptr, VOCABN, NROWS, VOCABN, DIMV, 0);
}

// round 8
// speedup vs baseline: 1.0449x; 1.0449x over previous
#include <cuda_runtime.h>
#include <cuda_bf16.h>
#include <cstdint>
#include <math.h>

#define BB      4
#define LL      1024
#define DIMV    512
#define VOCABN  10000
#define DEPTHN  3
#define DSTATE  16
#define DCONVN  4
#define DINNER  1024
#define DTRANK  32
#define HEADSN  8
#define DH      64
#define CTXN    98
#define NROWS   (BB*LL)          /* 4096 */

typedef unsigned int u32;

// ---------------- fp32 scratch ----------------
__device__ float g_h[NROWS*DIMV];
__device__ float g_xz[NROWS*2*DINNER];
__device__ float g_u[NROWS*DINNER];
__device__ float g_xdbl[NROWS*(DTRANK+2*DSTATE)];
__device__ float g_delta[NROWS*DINNER];
__device__ float g_q[NROWS*DIMV];
__device__ float g_kv[BB*CTXN*2*DIMV];
__device__ float g_probs[BB*HEADSN*LL*CTXN];

// ---------------- bf16 hi/lo plane scratch (activations) ----------------
__device__ __nv_bfloat16 g_nrm_h[NROWS*DIMV],  g_nrm_l[NROWS*DIMV];
__device__ __nv_bfloat16 g_u_h[NROWS*DINNER],  g_u_l[NROWS*DINNER];
__device__ __nv_bfloat16 g_xd_h[NROWS*64],     g_xd_l[NROWS*64];
__device__ __nv_bfloat16 g_y_h[NROWS*DINNER],  g_y_l[NROWS*DINNER];
__device__ __nv_bfloat16 g_ao_h[NROWS*DIMV],   g_ao_l[NROWS*DIMV];
__device__ __nv_bfloat16 g_ctx_h[BB*CTXN*DIMV],g_ctx_l[BB*CTXN*DIMV];

// ---------------- bf16 hi/lo plane scratch (weights) ----------------
__device__ __nv_bfloat16 g_wi_h[DEPTHN*2*DINNER*DIMV], g_wi_l[DEPTHN*2*DINNER*DIMV];
__device__ __nv_bfloat16 g_wxp_h[DEPTHN*64*DINNER],    g_wxp_l[DEPTHN*64*DINNER];
__device__ __nv_bfloat16 g_wdt_h[DEPTHN*DINNER*DTRANK],g_wdt_l[DEPTHN*DINNER*DTRANK];
__device__ __nv_bfloat16 g_wmo_h[DEPTHN*DIMV*DINNER],  g_wmo_l[DEPTHN*DIMV*DINNER];
__device__ __nv_bfloat16 g_wai_h[DEPTHN*3*DIMV*DIMV],  g_wai_l[DEPTHN*3*DIMV*DIMV];
__device__ __nv_bfloat16 g_wao_h[DEPTHN*DIMV*DIMV],    g_wao_l[DEPTHN*DIMV*DIMV];
__device__ __nv_bfloat16 g_wlg_h[VOCABN*DIMV],         g_wlg_l[VOCABN*DIMV];

__device__ __forceinline__ float siluf(float x) {
    return x / (1.0f + __expf(-x));
}

__device__ __forceinline__ void stage_split(float v, __nv_bfloat16* hp, __nv_bfloat16* lp) {
    __nv_bfloat16 h = __float2bfloat16(v);
    *hp = h;
    *lp = __float2bfloat16(v - __bfloat162float(h));
}

__device__ __forceinline__ u32 ld32bf(const __nv_bfloat16* p) {
    return *reinterpret_cast<const u32*>(p);
}

__device__ __forceinline__ void mma16816(float* c, const u32* a, const u32* b) {
    asm volatile(
        "mma.sync.aligned.m16n8k16.row.col.f32.bf16.bf16.f32 "
        "{%0,%1,%2,%3}, {%4,%5,%6,%7}, {%8,%9}, {%0,%1,%2,%3};\n"
        : "+f"(c[0]), "+f"(c[1]), "+f"(c[2]), "+f"(c[3])
        : "r"(a[0]), "r"(a[1]), "r"(a[2]), "r"(a[3]), "r"(b[0]), "r"(b[1]));
}

__device__ __forceinline__ void cp16(u32 dst, const void* src, int pbytes) {
    asm volatile("cp.async.cg.shared.global [%0], [%1], 16, %2;\n"
                 :: "r"(dst), "l"(src), "r"(pbytes));
}

// ---------------- fp32 -> (hi,lo) bf16 plane split ----------------
__global__ void split_k(const float* __restrict__ src,
                        __nv_bfloat16* __restrict__ hi,
                        __nv_bfloat16* __restrict__ lo, int n4)
{
    int i = blockIdx.x*blockDim.x + threadIdx.x;
    if (i >= n4) return;
    float4 v = ((const float4*)src)[i];
    __nv_bfloat16 h4[4], l4[4];
    stage_split(v.x, &h4[0], &l4[0]);
    stage_split(v.y, &h4[1], &l4[1]);
    stage_split(v.z, &h4[2], &l4[2]);
    stage_split(v.w, &h4[3], &l4[3]);
    ((uint2*)hi)[i] = *(uint2*)h4;
    ((uint2*)lo)[i] = *(uint2*)l4;
}

// =========================================================================
// Tensor-core GEMM on pre-split planes:
//   C[M,N] = (Ah+Al)[M,K] @ (Wh+Wl)[N,K]^T  (3-term, fp32 acc)
// flags: 1=beta (C += result), 2=softplus epilogue, 4=also write C planes
// Double-buffered cp.async staging. K % 32 == 0 required.
// __launch_bounds__(256, 2): cap regs at 128 so >=2 CTAs/SM (round-6 lesson).
// =========================================================================
#define BKT 32
#define PROW 40   /* padded bf16 elems per smem row (80B, 16B-aligned) */

template<int BM_, int BN_, int WGM, int WGN>
__global__ void __launch_bounds__(256, 2)
hgemm_k(const __nv_bfloat16* __restrict__ Ah_g, const __nv_bfloat16* __restrict__ Al_g, int lda,
        const __nv_bfloat16* __restrict__ Wh_g, const __nv_bfloat16* __restrict__ Wl_g, int ldw,
        const float* __restrict__ bias,
        float* __restrict__ C, __nv_bfloat16* __restrict__ Ch, __nv_bfloat16* __restrict__ Cl,
        int ldc, int M, int N, int K, int flags)
{
    constexpr int MT  = BM_/(WGM*16);
    constexpr int NT  = BN_/(WGN*8);
    constexpr int WMR = BM_/WGM;
    constexpr int WNC = BN_/WGN;

    extern __shared__ __nv_bfloat16 smem[];
    __nv_bfloat16* sA = smem;                   // [stage][plane][BM_*PROW]
    __nv_bfloat16* sW = smem + 2*2*BM_*PROW;    // [stage][plane][BN_*PROW]
    u32 sAu = (u32)__cvta_generic_to_shared(sA);
    u32 sWu = (u32)__cvta_generic_to_shared(sW);

    int bm = blockIdx.y*BM_, bn = blockIdx.x*BN_;
    int tid = threadIdx.x, warp = tid >> 5, lane = tid & 31;
    int wm = warp / WGN, wn = warp % WGN;
    int g = lane >> 2, cq = lane & 3;

    float acc[MT][NT][4];
#pragma unroll
    for (int mt = 0; mt < MT; mt++)
#pragma unroll
        for (int nt = 0; nt < NT; nt++)
#pragma unroll
            for (int j = 0; j < 4; j++) acc[mt][nt][j] = 0.f;

    auto load_stage = [&](int st, int k0) {
#pragma unroll
        for (int p = 0; p < 2; p++) {
            const __nv_bfloat16* s = p ? Al_g : Ah_g;
#pragma unroll
            for (int it = 0; it < (BM_*4)/256; it++) {
                int ci = tid + it*256;
                int r = ci >> 2, cc = (ci & 3) << 3;
                int gr = bm + r;
                u32 dst = sAu + (u32)((st*2+p)*BM_*PROW + r*PROW + cc)*2;
                cp16(dst, s + (long)(gr < M ? gr : 0)*lda + k0 + cc, gr < M ? 16 : 0);
            }
        }
#pragma unroll
        for (int p = 0; p < 2; p++) {
            const __nv_bfloat16* s = p ? Wl_g : Wh_g;
#pragma unroll
            for (int it = 0; it < (BN_*4)/256; it++) {
                int ci = tid + it*256;
                int r = ci >> 2, cc = (ci & 3) << 3;
                int gn = bn + r;
                u32 dst = sWu + (u32)((st*2+p)*BN_*PROW + r*PROW + cc)*2;
                cp16(dst, s + (long)(gn < N ? gn : 0)*ldw + k0 + cc, gn < N ? 16 : 0);
            }
        }
    };

    const int KT = K / BKT;
    load_stage(0, 0);
    asm volatile("cp.async.commit_group;\n");

    for (int kt = 0; kt < KT; kt++) {
        int cur = kt & 1;
        if (kt + 1 < KT) {
            load_stage((kt+1) & 1, (kt+1)*BKT);
            asm volatile("cp.async.commit_group;\n");
            asm volatile("cp.async.wait_group 1;\n");
        } else {
            asm volatile("cp.async.wait_group 0;\n");
        }
        __syncthreads();

        const __nv_bfloat16* Ahs = sA + (cur*2+0)*BM_*PROW;
        const __nv_bfloat16* Als = sA + (cur*2+1)*BM_*PROW;
        const __nv_bfloat16* Whs = sW + (cur*2+0)*BN_*PROW;
        const __nv_bfloat16* Wls = sW + (cur*2+1)*BN_*PROW;

#pragma unroll
        for (int ks = 0; ks < 2; ks++) {
            u32 ah[MT][4], al[MT][4], bh[NT][2], bl[NT][2];
#pragma unroll
            for (int mt = 0; mt < MT; mt++) {
                int base = (wm*WMR + mt*16 + g)*PROW + ks*16 + 2*cq;
                ah[mt][0] = ld32bf(&Ahs[base]);
                ah[mt][1] = ld32bf(&Ahs[base + 8*PROW]);
                ah[mt][2] = ld32bf(&Ahs[base + 8]);
                ah[mt][3] = ld32bf(&Ahs[base + 8*PROW + 8]);
                al[mt][0] = ld32bf(&Als[base]);
                al[mt][1] = ld32bf(&Als[base + 8*PROW]);
                al[mt][2] = ld32bf(&Als[base + 8]);
                al[mt][3] = ld32bf(&Als[base + 8*PROW + 8]);
            }
#pragma unroll
            for (int nt = 0; nt < NT; nt++) {
                int base = (wn*WNC + nt*8 + g)*PROW + ks*16 + 2*cq;
                bh[nt][0] = ld32bf(&Whs[base]);
                bh[nt][1] = ld32bf(&Whs[base + 8]);
                bl[nt][0] = ld32bf(&Wls[base]);
                bl[nt][1] = ld32bf(&Wls[base + 8]);
            }
#pragma unroll
            for (int mt = 0; mt < MT; mt++)
#pragma unroll
                for (int nt = 0; nt < NT; nt++) {
                    mma16816(acc[mt][nt], ah[mt], bh[nt]);
                    mma16816(acc[mt][nt], al[mt], bh[nt]);
                    mma16816(acc[mt][nt], ah[mt], bl[nt]);
                }
        }
        __syncthreads();
    }

    // ---- epilogue ----
#pragma unroll
    for (int mt = 0; mt < MT; mt++) {
        int r0 = bm + wm*WMR + mt*16 + g;
#pragma unroll
        for (int nt = 0; nt < NT; nt++) {
            int n0 = bn + wn*WNC + nt*8 + 2*cq;
            float bv0 = 0.f, bv1 = 0.f;
            if (bias) {
                if (n0   < N) bv0 = bias[n0];
                if (n0+1 < N) bv1 = bias[n0+1];
            }
#pragma unroll
            for (int half = 0; half < 2; half++) {
                int r = r0 + half*8;
                if (r >= M) continue;
                float v0 = acc[mt][nt][half*2+0] + bv0;
                float v1 = acc[mt][nt][half*2+1] + bv1;
                float* p = &C[(long)r*ldc + n0];
                if (flags & 1) {
                    if (n0   < N) v0 += p[0];
                    if (n0+1 < N) v1 += p[1];
                }
                if (flags & 2) {
                    v0 = (v0 > 20.f) ? v0 : log1pf(expf(v0));
                    v1 = (v1 > 20.f) ? v1 : log1pf(expf(v1));
                }
                if (n0+1 < N) {
                    *(float2*)p = make_float2(v0, v1);
                } else if (n0 < N) {
                    p[0] = v0;
                }
                if (flags & 4) {
                    long o = (long)r*ldc + n0;
                    if (n0   < N) stage_split(v0, &Ch[o],   &Cl[o]);
                    if (n0+1 < N) stage_split(v1, &Ch[o+1], &Cl[o+1]);
                }
            }
        }
    }
}

// ---------------- layernorm -> bf16 planes ----------------
__global__ void __launch_bounds__(256)
layernorm_k(const float* __restrict__ x, const float* __restrict__ g,
            const float* __restrict__ bta,
            __nv_bfloat16* __restrict__ nh, __nv_bfloat16* __restrict__ nl)
{
    int row = blockIdx.x;
    const float* xr = x + (long)row*DIMV;
    int tid = threadIdx.x;
    float v0 = xr[tid], v1 = xr[tid+256];

    __shared__ float red[8];
    float s = v0 + v1;
#pragma unroll
    for (int o = 16; o; o >>= 1) s += __shfl_xor_sync(0xffffffffu, s, o);
    if ((tid & 31) == 0) red[tid >> 5] = s;
    __syncthreads();
    if (tid < 8) {
        s = red[tid];
#pragma unroll
        for (int o = 4; o; o >>= 1) s += __shfl_xor_sync(0xffu, s, o);
        if (tid == 0) red[0] = s;
    }
    __syncthreads();
    float mu = red[0] * (1.0f/DIMV);
    float d0 = v0 - mu, d1 = v1 - mu;

    __shared__ float red2[8];
    float qv = d0*d0 + d1*d1;
#pragma unroll
    for (int o = 16; o; o >>= 1) qv += __shfl_xor_sync(0xffffffffu, qv, o);
    if ((tid & 31) == 0) red2[tid >> 5] = qv;
    __syncthreads();
    if (tid < 8) {
        qv = red2[tid];
#pragma unroll
        for (int o = 4; o; o >>= 1) qv += __shfl_xor_sync(0xffu, qv, o);
        if (tid == 0) red2[0] = qv;
    }
    __syncthreads();
    float rstd = rsqrtf(red2[0] * (1.0f/DIMV) + 1e-5f);
    float o0 = d0*rstd*g[tid]     + bta[tid];
    float o1 = d1*rstd*g[tid+256] + bta[tid+256];
    long base = (long)row*DIMV;
    stage_split(o0, &nh[base + tid],       &nl[base + tid]);
    stage_split(o1, &nh[base + tid + 256], &nl[base + tid + 256]);
}

// ---------------- embedding ----------------
__global__ void embed_k(const int* __restrict__ x, const float* __restrict__ tok,
                        const float* __restrict__ pos)
{
    int idx = blockIdx.x*blockDim.x + threadIdx.x;
    if (idx >= NROWS*DIMV) return;
    int d = idx & (DIMV-1);
    int row = idx >> 9;
    int l = row & (LL-1);
    int t = x[row];
    g_h[idx] = tok[(long)t*DIMV + d] + pos[(long)l*DIMV + d];
}

// ---------------- causal depthwise conv + silu -> u fp32 + planes ----------
__global__ void conv_silu_k(const float* __restrict__ w, const float* __restrict__ cb)
{
    int idx = blockIdx.x*blockDim.x + threadIdx.x;
    if (idx >= NROWS*DINNER) return;
    int d = idx & (DINNER-1);
    int row = idx >> 10;
    int l = row & (LL-1);
    int b = row >> 10;
    float acc = cb[d];
#pragma unroll
    for (int j = 0; j < DCONVN; j++) {
        int ll = l - (DCONVN-1) + j;
        if (ll >= 0)
            acc += w[d*DCONVN + j] * g_xz[((long)(b*LL + ll))*(2*DINNER) + d];
    }
    float r = siluf(acc);
    g_u[idx] = r;
    stage_split(r, &g_u_h[idx], &g_u_l[idx]);
}

// ---------------- selective scan, fused gate + plane output ----------------
__global__ void __launch_bounds__(256)
scan_k(const float* __restrict__ A_log, const float* __restrict__ D_skip)
{
    int b = blockIdx.y;
    int dbase = blockIdx.x * 16;
    int tid = threadIdx.x;
    int w = tid >> 5, lane = tid & 31;
    int d = dbase + (w << 1) + (lane >> 4);
    int s = lane & 15;

    float a  = -__expf(A_log[d*DSTATE + s]);
    float Dv = D_skip[d];
    float h  = 0.f;

    const float* dl = g_delta + (long)b*LL*DINNER + d;
    const float* uu = g_u     + (long)b*LL*DINNER + d;
    const float* bc = g_xdbl  + (long)b*LL*(DTRANK+2*DSTATE);
    const float* zz = g_xz    + ((long)b*LL)*(2*DINNER) + DINNER + d;
    __nv_bfloat16* yh = g_y_h + (long)b*LL*DINNER + d;
    __nv_bfloat16* yl = g_y_l + (long)b*LL*DINNER + d;

#pragma unroll 4
    for (int t = 0; t < LL; t++) {
        float dt = dl[(long)t*DINNER];
        float ut = uu[(long)t*DINNER];
        float Bt = bc[t*64 + DTRANK + s];
        float Ct = bc[t*64 + DTRANK + DSTATE + s];
        h = __expf(dt*a)*h + (dt*ut)*Bt;
        float p = h*Ct;
        p += __shfl_xor_sync(0xffffffffu, p, 8);
        p += __shfl_xor_sync(0xffffffffu, p, 4);
        p += __shfl_xor_sync(0xffffffffu, p, 2);
        p += __shfl_xor_sync(0xffffffffu, p, 1);
        if (s == 0) {
            float z = zz[(long)t*(2*DINNER)];
            float yv = (p + ut*Dv) * siluf(z);
            stage_split(yv, &yh[(long)t*DINNER], &yl[(long)t*DINNER]);
        }
    }
}

// ---------------- attention scores: grid (B*H, L/128), 128 thr ----------
__global__ void __launch_bounds__(128)
attn_scores_k()
{
    __shared__ float ks[CTXN*DH];
    int bh = blockIdx.x;
    int b = bh >> 3, hh = bh & 7;
    for (int i = threadIdx.x; i < CTXN*DH; i += 128)
        ks[i] = g_kv[((long)(b*CTXN + (i >> 6)))*(2*DIMV) + hh*DH + (i & 63)];
    __syncthreads();

    int l = blockIdx.y*128 + threadIdx.x;
    float qr[DH];
    const float* qp = g_q + ((long)(b*LL + l))*DIMV + hh*DH;
#pragma unroll
    for (int j = 0; j < DH; j++) qr[j] = qp[j];

    float* sp = g_probs + ((long)(bh*LL + l))*CTXN;
    for (int ss = 0; ss < CTXN; ss++) {
        float acc = 0.f;
#pragma unroll
        for (int j = 0; j < DH; j++) acc += qr[j]*ks[ss*DH + j];
        sp[ss] = acc * 0.125f;
    }
}

// ---------------- softmax over S=98: one warp per row ----------------
__global__ void __launch_bounds__(256)
softmax_k()
{
    int row = blockIdx.x*8 + (threadIdx.x >> 5);
    int lane = threadIdx.x & 31;
    float* p = g_probs + (long)row*CTXN;
    float v0 = p[lane];
    float v1 = p[lane+32];
    float v2 = p[lane+64];
    float v3 = (lane+96 < CTXN) ? p[lane+96] : -1e30f;
    float m = fmaxf(fmaxf(v0,v1), fmaxf(v2,v3));
#pragma unroll
    for (int o = 16; o; o >>= 1) m = fmaxf(m, __shfl_xor_sync(0xffffffffu, m, o));
    v0 = __expf(v0 - m); v1 = __expf(v1 - m); v2 = __expf(v2 - m);
    v3 = (lane+96 < CTXN) ? __expf(v3 - m) : 0.f;
    float s = v0+v1+v2+v3;
#pragma unroll
    for (int o = 16; o; o >>= 1) s += __shfl_xor_sync(0xffffffffu, s, o);
    float inv = 1.f/s;
    p[lane] = v0*inv; p[lane+32] = v1*inv; p[lane+64] = v2*inv;
    if (lane+96 < CTXN) p[lane+96] = v3*inv;
}

// ---------------- attn head-mean -> d_out region ----------------
__global__ void attn_mean_k(float* __restrict__ outp)
{
    int idx = blockIdx.x*blockDim.x + threadIdx.x;
    if (idx >= BB*LL*CTXN) return;
    int s = idx % CTXN;
    int bl = idx / CTXN;
    int l = bl & (LL-1);
    int b = bl >> 10;
    float acc = 0.f;
#pragma unroll
    for (int hh = 0; hh < HEADSN; hh++)
        acc += g_probs[((long)((b*HEADSN + hh)*LL + l))*CTXN + s];
    outp[idx] = acc * (1.0f/HEADSN);
}

// ---------------- attn @ V -> ao planes ----------------
__global__ void __launch_bounds__(128)
attn_av_k()
{
    __shared__ float vs[CTXN*DH];
    int bh = blockIdx.x;
    int b = bh >> 3, hh = bh & 7;
    for (int i = threadIdx.x; i < CTXN*DH; i += 128)
        vs[i] = g_kv[((long)(b*CTXN + (i >> 6)))*(2*DIMV) + DIMV + hh*DH + (i & 63)];
    __syncthreads();

    int l = blockIdx.y*128 + threadIdx.x;
    const float* pp = g_probs + ((long)(bh*LL + l))*CTXN;
    float acc[DH];
#pragma unroll
    for (int j = 0; j < DH; j++) acc[j] = 0.f;
    for (int ss = 0; ss < CTXN; ss++) {
        float pv = pp[ss];
#pragma unroll
        for (int j = 0; j < DH; j++) acc[j] += pv*vs[ss*DH + j];
    }
    long off = ((long)(b*LL + l))*DIMV + hh*DH;
#pragma unroll
    for (int j = 0; j < DH; j++)
        stage_split(acc[j], &g_ao_h[off + j], &g_ao_l[off + j]);
}

// =======================================================================
typedef __nv_bfloat16 bf;

extern "C" void kernel_launch(void* const* d_in, const int* in_sizes, int n_in,
                              void* d_out, int out_size)
{
    (void)in_sizes; (void)n_in; (void)out_size;
    const int*   x          = (const int*)  d_in[0];
    const float* context    = (const float*)d_in[1];
    const float* tok_emb    = (const float*)d_in[2];
    const float* pos_emb    = (const float*)d_in[3];
    const float* ln1_g      = (const float*)d_in[4];
    const float* ln1_b      = (const float*)d_in[5];
    const float* in_w       = (const float*)d_in[6];
    const float* conv_w     = (const float*)d_in[7];
    const float* conv_b     = (const float*)d_in[8];
    const float* xproj_w    = (const float*)d_in[9];
    const float* dt_w       = (const float*)d_in[10];
    const float* dt_b       = (const float*)d_in[11];
    const float* A_log      = (const float*)d_in[12];
    const float* D_skip     = (const float*)d_in[13];
    const float* mamba_out_w= (const float*)d_in[14];
    const float* ln2_g      = (const float*)d_in[15];
    const float* ln2_b      = (const float*)d_in[16];
    const float* attn_in_w  = (const float*)d_in[17];
    const float* attn_in_b  = (const float*)d_in[18];
    const float* attn_out_w = (const float*)d_in[19];
    const float* attn_out_b = (const float*)d_in[20];
    const float* lnf_g      = (const float*)d_in[21];
    const float* lnf_b      = (const float*)d_in[22];
    const float* logit_w    = (const float*)d_in[23];
    const float* logit_b    = (const float*)d_in[24];
    float* outp = (float*)d_out;

    // symbol addresses
    float *h, *xz, *u, *xdbl, *delta, *q, *kv;
    cudaGetSymbolAddress((void**)&h,    g_h);
    cudaGetSymbolAddress((void**)&xz,   g_xz);
    cudaGetSymbolAddress((void**)&u,    g_u);
    cudaGetSymbolAddress((void**)&xdbl, g_xdbl);
    cudaGetSymbolAddress((void**)&delta,g_delta);
    cudaGetSymbolAddress((void**)&q,    g_q);
    cudaGetSymbolAddress((void**)&kv,   g_kv);
    bf *nrmh,*nrml,*uh,*ul,*xdh,*xdl,*yh,*yl,*aoh,*aol,*ctxh,*ctxl;
    cudaGetSymbolAddress((void**)&nrmh, g_nrm_h); cudaGetSymbolAddress((void**)&nrml, g_nrm_l);
    cudaGetSymbolAddress((void**)&uh,   g_u_h);   cudaGetSymbolAddress((void**)&ul,   g_u_l);
    cudaGetSymbolAddress((void**)&xdh,  g_xd_h);  cudaGetSymbolAddress((void**)&xdl,  g_xd_l);
    cudaGetSymbolAddress((void**)&yh,   g_y_h);   cudaGetSymbolAddress((void**)&yl,   g_y_l);
    cudaGetSymbolAddress((void**)&aoh,  g_ao_h);  cudaGetSymbolAddress((void**)&aol,  g_ao_l);
    cudaGetSymbolAddress((void**)&ctxh, g_ctx_h); cudaGetSymbolAddress((void**)&ctxl, g_ctx_l);
    bf *wih,*wil,*wxph,*wxpl,*wdth,*wdtl,*wmoh,*wmol,*waih,*wail,*waoh,*waol,*wlgh,*wlgl;
    cudaGetSymbolAddress((void**)&wih,  g_wi_h);  cudaGetSymbolAddress((void**)&wil,  g_wi_l);
    cudaGetSymbolAddress((void**)&wxph, g_wxp_h); cudaGetSymbolAddress((void**)&wxpl, g_wxp_l);
    cudaGetSymbolAddress((void**)&wdth, g_wdt_h); cudaGetSymbolAddress((void**)&wdtl, g_wdt_l);
    cudaGetSymbolAddress((void**)&wmoh, g_wmo_h); cudaGetSymbolAddress((void**)&wmol, g_wmo_l);
    cudaGetSymbolAddress((void**)&waih, g_wai_h); cudaGetSymbolAddress((void**)&wail, g_wai_l);
    cudaGetSymbolAddress((void**)&waoh, g_wao_h); cudaGetSymbolAddress((void**)&waol, g_wao_l);
    cudaGetSymbolAddress((void**)&wlgh, g_wlg_h); cudaGetSymbolAddress((void**)&wlgl, g_wlg_l);

    // smem: 128x64 double-buffered = (128+64)*2 planes*2 stages*PROW*2B = 61,440
    constexpr int SM12864 = (128+64)*2*2*PROW*2;
    constexpr int SM64    = (64+64)*2*2*PROW*2;
    cudaFuncSetAttribute((const void*)hgemm_k<128,64,4,2>,
                         cudaFuncAttributeMaxDynamicSharedMemorySize, SM12864);
    cudaFuncSetAttribute((const void*)hgemm_k<64,64,4,2>,
                         cudaFuncAttributeMaxDynamicSharedMemorySize, SM64);

    const int NTH = 256;
    auto split = [&](const float* src, bf* hi, bf* lo, long n) {
        int n4 = (int)(n/4);
        split_k<<<(n4 + NTH-1)/NTH, NTH>>>(src, hi, lo, n4);
    };

    // ---- one-time weight/context splits ----
    split(in_w,       wih,  wil,  (long)DEPTHN*2*DINNER*DIMV);
    split(xproj_w,    wxph, wxpl, (long)DEPTHN*64*DINNER);
    split(dt_w,       wdth, wdtl, (long)DEPTHN*DINNER*DTRANK);
    split(mamba_out_w,wmoh, wmol, (long)DEPTHN*DIMV*DINNER);
    split(attn_in_w,  waih, wail, (long)DEPTHN*3*DIMV*DIMV);
    split(attn_out_w, waoh, waol, (long)DEPTHN*DIMV*DIMV);
    split(logit_w,    wlgh, wlgl, (long)VOCABN*DIMV);
    split(context,    ctxh, ctxl, (long)BB*CTXN*DIMV);

    auto gemm = [&](const bf* Ahp, const bf* Alp, int lda,
                    const bf* Whp, const bf* Wlp, int ldw,
                    const float* bias, float* C, bf* Chp, bf* Clp, int ldc,
                    int M, int N, int K, int flags) {
        dim3 grid((N + 63)/64, (M + 127)/128);
        hgemm_k<128,64,4,2><<<grid, 256, SM12864>>>(Ahp,Alp,lda, Whp,Wlp,ldw,
                                                    bias, C,Chp,Clp, ldc, M,N,K, flags);
    };

    embed_k<<<(NROWS*DIMV + NTH-1)/NTH, NTH>>>(x, tok_emb, pos_emb);

    for (int i = 0; i < DEPTHN; i++) {
        // ---- mamba block ----
        layernorm_k<<<NROWS, 256>>>(h, ln1_g + i*DIMV, ln1_b + i*DIMV, nrmh, nrml);
        gemm(nrmh, nrml, DIMV, wih + (long)i*2*DINNER*DIMV, wil + (long)i*2*DINNER*DIMV,
             DIMV, nullptr, xz, nullptr, nullptr, 2*DINNER, NROWS, 2*DINNER, DIMV, 0);
        conv_silu_k<<<(NROWS*DINNER + NTH-1)/NTH, NTH>>>(
            conv_w + (long)i*DINNER*DCONVN, conv_b + (long)i*DINNER);
        {   // xproj: N=64 -> 64x64 tiles
            dim3 grid(1, NROWS/64);
            hgemm_k<64,64,4,2><<<grid, 256, SM64>>>(
                uh, ul, DINNER, wxph + (long)i*64*DINNER, wxpl + (long)i*64*DINNER,
                DINNER, nullptr, xdbl, xdh, xdl, 64, NROWS, 64, DINNER, 4 /*planes*/);
        }
        gemm(xdh, xdl, 64, wdth + (long)i*DINNER*DTRANK, wdtl + (long)i*DINNER*DTRANK,
             DTRANK, dt_b + (long)i*DINNER, delta, nullptr, nullptr, DINNER,
             NROWS, DINNER, DTRANK, 2 /*softplus*/);
        scan_k<<<dim3(DINNER/16, BB), 256>>>(
            A_log + (long)i*DINNER*DSTATE, D_skip + (long)i*DINNER);
        gemm(yh, yl, DINNER, wmoh + (long)i*DIMV*DINNER, wmol + (long)i*DIMV*DINNER,
             DINNER, nullptr, h, nullptr, nullptr, DIMV, NROWS, DIMV, DINNER, 1 /*beta*/);

        // ---- cross attention ----
        layernorm_k<<<NROWS, 256>>>(h, ln2_g + i*DIMV, ln2_b + i*DIMV, nrmh, nrml);
        long aiw_off = (long)i*3*DIMV*DIMV;
        const float* ab = attn_in_b + (long)i*3*DIMV;
        gemm(nrmh, nrml, DIMV, waih + aiw_off, wail + aiw_off, DIMV,
             ab, q, nullptr, nullptr, DIMV, NROWS, DIMV, DIMV, 0);
        // fused K+V projection: M=392, N=1024
        gemm(ctxh, ctxl, DIMV, waih + aiw_off + (long)DIMV*DIMV,
             wail + aiw_off + (long)DIMV*DIMV, DIMV,
             ab + DIMV, kv, nullptr, nullptr, 2*DIMV, BB*CTXN, 2*DIMV, DIMV, 0);
        attn_scores_k<<<dim3(BB*HEADSN, LL/128), 128>>>();
        softmax_k<<<(BB*HEADSN*LL)/8, 256>>>();
        attn_mean_k<<<(BB*LL*CTXN + NTH-1)/NTH, NTH>>>(
            outp + (long)BB*LL*VOCABN + (long)i*BB*LL*CTXN);
        attn_av_k<<<dim3(BB*HEADSN, LL/128), 128>>>();
        gemm(aoh, aol, DIMV, waoh + (long)i*DIMV*DIMV, waol + (long)i*DIMV*DIMV,
             DIMV, attn_out_b + (long)i*DIMV, h, nullptr, nullptr, DIMV,
             NROWS, DIMV, DIMV, 1 /*beta*/);
    }

    // ---- final LN + logits ----
    layernorm_k<<<NROWS, 256>>>(h, lnf_g, lnf_b, nrmh, nrml);
    gemm(nrmh, nrml, DIMV, wlgh, wlgl, DIMV, logit_b, outp,
         nullptr, nullptr, VOCABN, NROWS, VOCABN, DIMV, 0);
}